// round 1
// baseline (speedup 1.0000x reference)
#include <cuda_runtime.h>
#include <cstdint>

#define CRF_B 256
#define CRF_T 512
#define CRF_L 64

// ---- packed f32x2 helpers (Blackwell dual-FP32) ----
__device__ __forceinline__ unsigned long long pack2(float lo, float hi) {
    unsigned long long r;
    asm("mov.b64 %0, {%1, %2};" : "=l"(r) : "f"(lo), "f"(hi));
    return r;
}
__device__ __forceinline__ void unpack2(unsigned long long v, float& lo, float& hi) {
    asm("mov.b64 {%0, %1}, %2;" : "=f"(lo), "=f"(hi) : "l"(v));
}
__device__ __forceinline__ unsigned long long fma2(unsigned long long a,
                                                   unsigned long long b,
                                                   unsigned long long c) {
    unsigned long long d;
    asm("fma.rn.f32x2 %0, %1, %2, %3;" : "=l"(d) : "l"(a), "l"(b), "l"(c));
    return d;
}
__device__ __forceinline__ unsigned long long add2(unsigned long long a,
                                                   unsigned long long b) {
    unsigned long long d;
    asm("add.rn.f32x2 %0, %1, %2;" : "=l"(d) : "l"(a), "l"(b));
    return d;
}
__device__ __forceinline__ float rcp_fast(float x) {
    float r;
    asm("rcp.approx.f32 %0, %1;" : "=f"(r) : "f"(x));
    return r;
}

// One warp per batch row. Lane handles labels (lane, lane+32).
// State w_t kept in prob domain with running log offset M (deferred 1-step
// renormalization so the shfl max-reduce hides under the FFMA2 stream).
__global__ __launch_bounds__(32, 1)
void CRF_48266842472844_kernel(const float* __restrict__ y_true,
                               const float* __restrict__ y_pred,
                               const float* __restrict__ trans,
                               float* __restrict__ out) {
    const int b    = blockIdx.x;
    const int lane = threadIdx.x;
    const int jA   = lane;
    const int jB   = lane + 32;

    __shared__ __align__(16) float qbuf[2][CRF_L];

    // ---- load E = exp(trans) columns jA, jB into registers, packed over i ----
    unsigned long long Ea[32], Eb[32];
#pragma unroll
    for (int k = 0; k < 32; k++) {
        float a0 = __expf(__ldg(&trans[(2 * k) * CRF_L + jA]));
        float a1 = __expf(__ldg(&trans[(2 * k + 1) * CRF_L + jA]));
        Ea[k] = pack2(a0, a1);
        float b0 = __expf(__ldg(&trans[(2 * k) * CRF_L + jB]));
        float b1 = __expf(__ldg(&trans[(2 * k + 1) * CRF_L + jB]));
        Eb[k] = pack2(b0, b1);
    }

    const float* yp = y_pred + (size_t)b * CRF_T * CRF_L;
    const float* yt = y_true + (size_t)b * CRF_T * CRF_L;

    // ---- t = 0 init ----
    float e0A = yp[jA], e0B = yp[jB];
    float t0A = yt[jA], t0B = yt[jB];
    float pacc = e0A * t0A + e0B * t0B;   // point score accumulator (per-lane)
    unsigned uA = __ballot_sync(0xffffffffu, t0A > 0.5f);
    unsigned uB = __ballot_sync(0xffffffffu, t0B > 0.5f);
    int prev = uA ? (__ffs(uA) - 1) : (__ffs(uB) + 31);

    float vA = __expf(e0A);
    float vB = __expf(e0B);
    qbuf[0][jA] = vA;
    qbuf[0][jB] = vB;

    float M  = 0.0f;   // running log normalization
    float ts = 0.0f;   // transition score

    // prefetch buffers for t+1, t+2
    float peA[2], peB[2], ptA[2], ptB[2];
#pragma unroll
    for (int pf = 0; pf < 2; pf++) {
        peA[pf] = yp[(1 + pf) * CRF_L + jA];
        peB[pf] = yp[(1 + pf) * CRF_L + jB];
        ptA[pf] = yt[(1 + pf) * CRF_L + jA];
        ptB[pf] = yt[(1 + pf) * CRF_L + jB];
    }
    __syncwarp();

    int cur = 0;
#pragma unroll 2
    for (int t = 1; t < CRF_T; t++) {
        const int pb = (t - 1) & 1;
        const float eA = peA[pb], eB = peB[pb];
        const float yA = ptA[pb], yB = ptB[pb];

        // prefetch t+2 into the slot just freed (clamped, branch-free)
        {
            int tn = t + 2;
            tn = (tn < CRF_T) ? tn : (CRF_T - 1);
            peA[pb] = yp[tn * CRF_L + jA];
            peB[pb] = yp[tn * CRF_L + jB];
            ptA[pb] = yt[tn * CRF_L + jA];
            ptB[pb] = yt[tn * CRF_L + jB];
        }

        // deferred normalizer: max of previous w (hides under FFMA2 stream)
        float c = fmaxf(vA, vB);
#pragma unroll
        for (int s = 16; s > 0; s >>= 1)
            c = fmaxf(c, __shfl_xor_sync(0xffffffffu, c, s));

        // ---- matmul: s[j] = sum_i w[i] * E[i][j], packed over i ----
        unsigned long long a0 = 0ull, a1 = 0ull, b0 = 0ull, b1 = 0ull;
        const ulonglong2* q2 = (const ulonglong2*)qbuf[cur];
#pragma unroll
        for (int k = 0; k < 16; k++) {
            ulonglong2 qv = q2[k];   // LDS.128 broadcast: (w[4k..4k+3])
            a0 = fma2(qv.x, Ea[2 * k],     a0);
            b0 = fma2(qv.x, Eb[2 * k],     b0);
            a1 = fma2(qv.y, Ea[2 * k + 1], a1);
            b1 = fma2(qv.y, Eb[2 * k + 1], b1);
        }
        a0 = add2(a0, a1);
        b0 = add2(b0, b1);
        float sA, sAh, sB, sBh;
        unpack2(a0, sA, sAh); sA += sAh;
        unpack2(b0, sB, sBh); sB += sBh;

        float inv = rcp_fast(c);
        M += __logf(c);
        vA = sA * __expf(eA) * inv;
        vB = sB * __expf(eB) * inv;

        // ---- fused scores ----
        pacc += eA * yA + eB * yB;
        unsigned wAm = __ballot_sync(0xffffffffu, yA > 0.5f);
        unsigned wBm = __ballot_sync(0xffffffffu, yB > 0.5f);
        int lab = wAm ? (__ffs(wAm) - 1) : (__ffs(wBm) + 31);
        ts += __ldg(&trans[prev * CRF_L + lab]);
        prev = lab;

        // ---- store new state (double buffer) ----
        cur ^= 1;
        qbuf[cur][jA] = vA;
        qbuf[cur][jB] = vB;
        __syncwarp();
    }

    // ---- log_norm = M + log(sum_j w_{T-1}[j]) ----
    float ssum = vA + vB;
#pragma unroll
    for (int s = 16; s > 0; s >>= 1)
        ssum += __shfl_xor_sync(0xffffffffu, ssum, s);
    float lse = M + __logf(ssum);

#pragma unroll
    for (int s = 16; s > 0; s >>= 1)
        pacc += __shfl_xor_sync(0xffffffffu, pacc, s);

    if (lane == 0)
        out[b] = lse - pacc - ts;   // -(point + trans - log_norm)
}

extern "C" void kernel_launch(void* const* d_in, const int* in_sizes, int n_in,
                              void* d_out, int out_size) {
    const float* y_true = (const float*)d_in[0];
    const float* y_pred = (const float*)d_in[1];
    const float* trans  = (const float*)d_in[2];
    float* out = (float*)d_out;
    (void)in_sizes; (void)n_in; (void)out_size;
    CRF_48266842472844_kernel<<<CRF_B, 32>>>(y_true, y_pred, trans, out);
}